// round 14
// baseline (speedup 1.0000x reference)
#include <cuda_runtime.h>

#define NLEV   12
#define HSIZE  524288
#define HMASK  (HSIZE - 1)

// TRANSPOSED duplicated {w,w} layout, float offsets (all even -> 8B aligned)
// W1T[j][i]: j=0..23 feature, i=0..31 output  -> OFF_W1 + (j*32+i)*2
// W2T[j][i]: j=0..31, i=0..15                 -> OFF_W2 + (j*16+i)*2
// W3T[j][i]: j=0..15, i=0..7                  -> OFF_W3 + (j*8+i)*2
#define OFF_W1  0       // 24*32*2 = 1536
#define OFF_B1  1536    // 64
#define OFF_W2  1600    // 1024
#define OFF_B2  2624    // 32
#define OFF_W3  2656    // 256
#define OFF_B3  2912    // 16
#define OFF_W4  2928    // 16
#define OFF_B4  2944    // 2
#define NW_FLOATS 2948
#define NW_PAD   2952

__constant__ __align__(16) float cW[NW_PAD];
__device__  float g_dup[NW_PAD];

union F2 { unsigned long long u; float2 f; float s[2]; };

__device__ __forceinline__ void fma2(F2& d, const F2 a, const F2 b, const F2 c) {
    asm("fma.rn.f32x2 %0, %1, %2, %3;" : "=l"(d.u) : "l"(a.u), "l"(b.u), "l"(c.u));
}

__device__ __forceinline__ F2 cpair(int floatOff) {
    F2 r;
    r.u = *reinterpret_cast<const unsigned long long*>(cW + floatOff);
    return r;
}

__device__ __forceinline__ F2 lrelu2(F2 v, const F2 slope) {
    F2 m, r;
    asm("mul.rn.f32x2 %0, %1, %2;" : "=l"(m.u) : "l"(v.u), "l"(slope.u));
    r.s[0] = fmaxf(v.s[0], m.s[0]);
    r.s[1] = fmaxf(v.s[1], m.s[1]);
    return r;
}

// build transposed, duplicated weight layout in g_dup
__global__ void prep_kernel(const float* __restrict__ W1, const float* __restrict__ b1,
                            const float* __restrict__ W2, const float* __restrict__ b2,
                            const float* __restrict__ W3, const float* __restrict__ b3,
                            const float* __restrict__ W4, const float* __restrict__ b4)
{
    int k = blockIdx.x * blockDim.x + threadIdx.x;
    float w; int off;
    if (k < 768) {                       // W1 [32 x 24] -> W1T
        int i = k / 24, j = k % 24;
        w = W1[k]; off = OFF_W1 + (j * 32 + i) * 2;
    } else if (k < 800) {
        w = b1[k - 768]; off = OFF_B1 + 2 * (k - 768);
    } else if (k < 1312) {               // W2 [16 x 32] -> W2T
        int s = k - 800, i = s / 32, j = s % 32;
        w = W2[s]; off = OFF_W2 + (j * 16 + i) * 2;
    } else if (k < 1328) {
        w = b2[k - 1312]; off = OFF_B2 + 2 * (k - 1312);
    } else if (k < 1456) {               // W3 [8 x 16] -> W3T
        int s = k - 1328, i = s / 16, j = s % 16;
        w = W3[s]; off = OFF_W3 + (j * 8 + i) * 2;
    } else if (k < 1464) {
        w = b3[k - 1456]; off = OFF_B3 + 2 * (k - 1456);
    } else if (k < 1472) {
        w = W4[k - 1464]; off = OFF_W4 + 2 * (k - 1464);
    } else if (k < 1473) {
        w = b4[0]; off = OFF_B4;
    } else return;
    g_dup[off]     = w;
    g_dup[off + 1] = w;
}

// 4 points per thread: each weight LDC feeds two FFMA2 (pairs A and B).
__global__ __launch_bounds__(128, 2)
void nhgrid_kernel(const float* __restrict__ x,
                   const float* __restrict__ tables,
                   float* __restrict__ out, int n_points)
{
    int quad = blockIdx.x * blockDim.x + threadIdx.x;
    int n0 = 4 * quad;
    if (n0 >= n_points) return;
    bool full = (n0 + 3 < n_points);

    // coords for 4 points: pair A = (p0,p1), pair B = (p2,p3)
    float px[4], py[4];
    if (full) {
        float4 q0 = *reinterpret_cast<const float4*>(x + 2 * n0);
        float4 q1 = *reinterpret_cast<const float4*>(x + 2 * n0 + 4);
        px[0] = q0.x; py[0] = q0.y; px[1] = q0.z; py[1] = q0.w;
        px[2] = q1.x; py[2] = q1.y; px[3] = q1.z; py[3] = q1.w;
    } else {
        #pragma unroll
        for (int k = 0; k < 4; k++) {
            int n = n0 + k;
            int m = (n < n_points) ? n : (n_points - 1);
            px[k] = x[2 * m]; py[k] = x[2 * m + 1];
        }
    }
    float u0[4], u1[4];
    #pragma unroll
    for (int k = 0; k < 4; k++) {
        u0[k] = px[k] * 0.5f + 0.5f;
        u1[k] = py[k] * 0.5f + 0.5f;
    }

    F2 slope; slope.s[0] = 0.01f; slope.s[1] = 0.01f;

    // spacings = 256.0 // 1.6**(11-i), Python-double floor-division semantics
    const float spacings[NLEV] = {1.f, 2.f, 3.f, 5.f, 9.f, 15.f, 24.f, 39.f,
                                  62.f, 99.f, 159.f, 256.f};

    // layer-1 accumulators for both pairs, initialized with biases
    F2 h1a[32], h1b[32];
    #pragma unroll
    for (int i = 0; i < 32; i++) {
        F2 b = cpair(OFF_B1 + 2 * i);
        h1a[i] = b;
        h1b[i] = b;
    }

    // gather + accumulate in 2 chunks of 6 levels (12 feature pairs per point-pair)
    #pragma unroll
    for (int c = 0; c < 2; c++) {
        F2 fa[12], fb[12];
        #pragma unroll
        for (int l = 0; l < 6; l++) {
            int lev = 6 * c + l;
            float s = spacings[lev];
            const float2* base = reinterpret_cast<const float2*>(tables) + (size_t)lev * HSIZE;
            unsigned h[4];
            #pragma unroll
            for (int k = 0; k < 4; k++) {
                int d0 = (int)floorf(u0[k] * s);
                int d1 = (int)floorf(u1[k] * s);
                h[k] = ((unsigned)d0 * 73856093u + (unsigned)d1 * 19349663u) & HMASK;
            }
            float2 t0 = base[h[0]];
            float2 t1 = base[h[1]];
            float2 t2 = base[h[2]];
            float2 t3 = base[h[3]];
            fa[2 * l].f     = make_float2(t0.x, t1.x);
            fa[2 * l + 1].f = make_float2(t0.y, t1.y);
            fb[2 * l].f     = make_float2(t2.x, t3.x);
            fb[2 * l + 1].f = make_float2(t2.y, t3.y);
        }
        #pragma unroll
        for (int l = 0; l < 12; l++) {
            int j = 12 * c + l;            // global feature index
            F2 fja = fa[l];
            F2 fjb = fb[l];
            #pragma unroll
            for (int i = 0; i < 32; i++) {
                F2 w = cpair(OFF_W1 + (j * 32 + i) * 2);   // ONE load, TWO fma2
                fma2(h1a[i], w, fja, h1a[i]);
                fma2(h1b[i], w, fjb, h1b[i]);
            }
        }
    }
    #pragma unroll
    for (int i = 0; i < 32; i++) {
        h1a[i] = lrelu2(h1a[i], slope);
        h1b[i] = lrelu2(h1b[i], slope);
    }

    // layer 2: 32 -> 16
    F2 h2a[16], h2b[16];
    #pragma unroll
    for (int i = 0; i < 16; i++) {
        F2 b = cpair(OFF_B2 + 2 * i);
        h2a[i] = b;
        h2b[i] = b;
    }
    #pragma unroll
    for (int j = 0; j < 32; j++) {
        F2 hja = h1a[j];
        F2 hjb = h1b[j];
        #pragma unroll
        for (int i = 0; i < 16; i++) {
            F2 w = cpair(OFF_W2 + (j * 16 + i) * 2);
            fma2(h2a[i], w, hja, h2a[i]);
            fma2(h2b[i], w, hjb, h2b[i]);
        }
    }
    #pragma unroll
    for (int i = 0; i < 16; i++) {
        h2a[i] = lrelu2(h2a[i], slope);
        h2b[i] = lrelu2(h2b[i], slope);
    }

    // layer 3: 16 -> 8
    F2 h3a[8], h3b[8];
    #pragma unroll
    for (int i = 0; i < 8; i++) {
        F2 b = cpair(OFF_B3 + 2 * i);
        h3a[i] = b;
        h3b[i] = b;
    }
    #pragma unroll
    for (int j = 0; j < 16; j++) {
        F2 hja = h2a[j];
        F2 hjb = h2b[j];
        #pragma unroll
        for (int i = 0; i < 8; i++) {
            F2 w = cpair(OFF_W3 + (j * 8 + i) * 2);
            fma2(h3a[i], w, hja, h3a[i]);
            fma2(h3b[i], w, hjb, h3b[i]);
        }
    }
    #pragma unroll
    for (int i = 0; i < 8; i++) {
        h3a[i] = lrelu2(h3a[i], slope);
        h3b[i] = lrelu2(h3b[i], slope);
    }

    // layer 4: 8 -> 1, then double lrelu
    F2 za = cpair(OFF_B4);
    F2 zb = za;
    #pragma unroll
    for (int j = 0; j < 8; j++) {
        F2 w = cpair(OFF_W4 + 2 * j);
        fma2(za, w, h3a[j], za);
        fma2(zb, w, h3b[j], zb);
    }
    za = lrelu2(za, slope); za = lrelu2(za, slope);
    zb = lrelu2(zb, slope); zb = lrelu2(zb, slope);

    if (full) {
        float4 o;
        o.x = za.s[0]; o.y = za.s[1]; o.z = zb.s[0]; o.w = zb.s[1];
        *reinterpret_cast<float4*>(out + n0) = o;
    } else {
        float v[4] = {za.s[0], za.s[1], zb.s[0], zb.s[1]};
        #pragma unroll
        for (int k = 0; k < 4; k++)
            if (n0 + k < n_points) out[n0 + k] = v[k];
    }
}

extern "C" void kernel_launch(void* const* d_in, const int* in_sizes, int n_in,
                              void* d_out, int out_size)
{
    const float* x      = (const float*)d_in[0];
    const float* tables = (const float*)d_in[1];
    const float* W1     = (const float*)d_in[2];
    const float* b1     = (const float*)d_in[3];
    const float* W2     = (const float*)d_in[4];
    const float* b2     = (const float*)d_in[5];
    const float* W3     = (const float*)d_in[6];
    const float* b3     = (const float*)d_in[7];
    const float* W4     = (const float*)d_in[8];
    const float* b4     = (const float*)d_in[9];
    float* out = (float*)d_out;

    int n_points = in_sizes[0] / 2;

    // 1) build transposed duplicated weight layout in device global
    prep_kernel<<<(1473 + 255) / 256, 256>>>(W1, b1, W2, b2, W3, b3, W4, b4);

    // 2) move it into constant memory (D2D async memcpy, graph-capturable)
    void* dup_ptr = nullptr;
    cudaGetSymbolAddress(&dup_ptr, g_dup);
    cudaMemcpyToSymbolAsync(cW, dup_ptr, NW_PAD * sizeof(float), 0,
                            cudaMemcpyDeviceToDevice, 0);

    // 3) main kernel: 4 points per thread
    int n_quads = (n_points + 3) / 4;
    int threads = 128;
    int blocks = (n_quads + threads - 1) / threads;
    nhgrid_kernel<<<blocks, threads>>>(x, tables, out, n_points);
}